// round 15
// baseline (speedup 1.0000x reference)
#include <cuda_runtime.h>
#include <cuda_fp16.h>
#include <math.h>

// Problem constants
#define BATCH    64
#define BHALF    32             // batch tile: 32 b -> 64 MB u_hat slice (fits L2)
#define IN_CAPS  2048
#define IN_DIM   16
#define NUM_CAPS 32
#define OUT_DIM  16
#define JD       512            // NUM_CAPS * OUT_DIM
#define NIC      32             // i-chunks per batch in iter kernel
#define IC       (IN_CAPS/NIC)  // 64 i's per block

// Scratch (device globals; allocation-free per harness rules)
__device__ __align__(16) __half g_uhat[(size_t)BATCH * IN_CAPS * JD];  // 128 MB, [b][i][j*16+d]
__device__ float g_spart[(size_t)BATCH * NIC * JD];  // 4 MB, d-major [b][ic][d*32+j]
__device__ float g_out0[(size_t)BATCH * JD];         // d-major [b][d*32+j]
__device__ float g_out1[(size_t)BATCH * JD];

// ---- packed f32x2 helpers (sm_103a) ---------------------------------------
static __device__ __forceinline__ unsigned long long pack2(float lo, float hi) {
    unsigned long long r;
    asm("mov.b64 %0, {%1, %2};" : "=l"(r) : "f"(lo), "f"(hi));
    return r;
}
#define FMA2(d, a, b, c) asm("fma.rn.f32x2 %0, %1, %2, %3;" : "=l"(d) : "l"(a), "l"(b), "l"(c))
#define MUL2(d, a, b)    asm("mul.rn.f32x2 %0, %1, %2;"     : "=l"(d) : "l"(a), "l"(b))

// evict-first float4 load: keeps streamed W/x from displacing u_hat in L2
static __device__ __forceinline__ float4 ldcs4(const float4* p) {
    float4 v;
    asm("ld.global.cs.v4.f32 {%0,%1,%2,%3}, [%4];"
        : "=f"(v.x), "=f"(v.y), "=f"(v.z), "=f"(v.w) : "l"(p));
    return v;
}

// ---------------------------------------------------------------------------
// K1 (proven per-i config), half-batch version: u_hat[b0..b0+32).
// One block per i, 512 threads (t = jd). x staged in smem pre-packed as
// (b, b+1) f32x2 pairs; W row held in regs as (w,w) pairs; fma.rn.f32x2
// does 2 batches per 16 packed FMAs. W/x loaded with .cs (evict-first).
// ---------------------------------------------------------------------------
__global__ __launch_bounds__(512) void uhat_kernel(
    const float* __restrict__ x, const float* __restrict__ W, int b0)
{
    const int i = blockIdx.x;
    const int t = threadIdx.x;          // 0..511

    __shared__ unsigned long long xp[BHALF / 2][16];   // 16 b-pairs x 16 k

    if (t < 256) {
        int p = t >> 4, k = t & 15;     // 256 threads cover 16*16
        float lo = x[((size_t)(b0 + 2 * p)     * IN_CAPS + i) * IN_DIM + k];
        float hi = x[((size_t)(b0 + 2 * p + 1) * IN_CAPS + i) * IN_DIM + k];
        xp[p][k] = pack2(lo, hi);
    }

    const float4* Wr = (const float4*)(W + ((size_t)i * JD + t) * IN_DIM);
    float4 w0 = ldcs4(Wr + 0), w1 = ldcs4(Wr + 1);
    float4 w2 = ldcs4(Wr + 2), w3 = ldcs4(Wr + 3);
    unsigned long long wp[16];
    wp[0]  = pack2(w0.x, w0.x); wp[1]  = pack2(w0.y, w0.y);
    wp[2]  = pack2(w0.z, w0.z); wp[3]  = pack2(w0.w, w0.w);
    wp[4]  = pack2(w1.x, w1.x); wp[5]  = pack2(w1.y, w1.y);
    wp[6]  = pack2(w1.z, w1.z); wp[7]  = pack2(w1.w, w1.w);
    wp[8]  = pack2(w2.x, w2.x); wp[9]  = pack2(w2.y, w2.y);
    wp[10] = pack2(w2.z, w2.z); wp[11] = pack2(w2.w, w2.w);
    wp[12] = pack2(w3.x, w3.x); wp[13] = pack2(w3.y, w3.y);
    wp[14] = pack2(w3.z, w3.z); wp[15] = pack2(w3.w, w3.w);

    __syncthreads();

    __half* out = g_uhat + ((size_t)b0 * IN_CAPS + i) * JD + t;
    #pragma unroll 4
    for (int p = 0; p < BHALF / 2; p++) {
        const ulonglong2* ap = (const ulonglong2*)xp[p];
        ulonglong2 a0 = ap[0], a1 = ap[1], a2 = ap[2], a3 = ap[3];
        ulonglong2 a4 = ap[4], a5 = ap[5], a6 = ap[6], a7 = ap[7];
        unsigned long long acc;
        MUL2(acc, wp[0],  a0.x);
        FMA2(acc, wp[1],  a0.y, acc);
        FMA2(acc, wp[2],  a1.x, acc);
        FMA2(acc, wp[3],  a1.y, acc);
        FMA2(acc, wp[4],  a2.x, acc);
        FMA2(acc, wp[5],  a2.y, acc);
        FMA2(acc, wp[6],  a3.x, acc);
        FMA2(acc, wp[7],  a3.y, acc);
        FMA2(acc, wp[8],  a4.x, acc);
        FMA2(acc, wp[9],  a4.y, acc);
        FMA2(acc, wp[10], a5.x, acc);
        FMA2(acc, wp[11], a5.y, acc);
        FMA2(acc, wp[12], a6.x, acc);
        FMA2(acc, wp[13], a6.y, acc);
        FMA2(acc, wp[14], a7.x, acc);
        FMA2(acc, wp[15], a7.y, acc);
        float lo, hi;
        asm("mov.b64 {%0, %1}, %2;" : "=f"(lo), "=f"(hi) : "l"(acc));
        out[(size_t)(2 * p)     * IN_CAPS * JD] = __float2half_rn(lo);
        out[(size_t)(2 * p + 1) * IN_CAPS * JD] = __float2half_rn(hi);
    }
}

// ---------------------------------------------------------------------------
// Fused routing iteration (proven R12 config), half-batch: grid (NIC, 32).
// Software pipelined (8 outstanding LDG.128/warp). Lane = j; agreement dot
// in half2; softmax without max subtraction (exact). With the 64 MB slice
// L2-resident from the previous pass, loads are L2 hits.
// iter1 logits = <u,out0>; iter2 = <u,out0+out1>.
// ---------------------------------------------------------------------------
__global__ __launch_bounds__(256, 3) void iter_kernel(int iter, int rev, int b0)
{
    const int b    = b0 + (rev ? (BHALF - 1 - blockIdx.y) : blockIdx.y);
    const int ic   = rev ? (NIC - 1 - blockIdx.x) : blockIdx.x;
    const int t    = threadIdx.x;
    const int w    = t >> 5;
    const int lane = t & 31;            // = j
    const int i0   = ic * IC;

    __half2 vout2[8];
    if (iter > 0) {
        #pragma unroll
        for (int d2 = 0; d2 < 8; d2++) {
            float f0 = g_out0[(size_t)b * JD + (2 * d2)     * 32 + lane];
            float f1 = g_out0[(size_t)b * JD + (2 * d2 + 1) * 32 + lane];
            if (iter == 2) {
                f0 += g_out1[(size_t)b * JD + (2 * d2)     * 32 + lane];
                f1 += g_out1[(size_t)b * JD + (2 * d2 + 1) * 32 + lane];
            }
            vout2[d2] = __floats2half2_rn(f0, f1);
        }
    }

    float acc[16];
    #pragma unroll
    for (int d = 0; d < 16; d++) acc[d] = 0.f;

    const __half* uhbase = g_uhat + ((size_t)b * IN_CAPS + i0) * JD + lane * 16;

    // prologue: loads for step 0
    uint4 ra0, ra1, rb0, rb1;
    {
        const uint4* pA = (const uint4*)(uhbase + (size_t)w * JD);
        const uint4* pB = (const uint4*)(uhbase + (size_t)(w + 8) * JD);
        ra0 = pA[0]; ra1 = pA[1];
        rb0 = pB[0]; rb1 = pB[1];
    }

    #pragma unroll
    for (int step = 0; step < 4; step++) {
        // prefetch step+1 BEFORE consuming the current data
        uint4 na0, na1, nb0, nb1;
        if (step < 3) {
            const int iiA = w + (step + 1) * 16;
            const uint4* pA = (const uint4*)(uhbase + (size_t)iiA * JD);
            const uint4* pB = (const uint4*)(uhbase + (size_t)(iiA + 8) * JD);
            na0 = pA[0]; na1 = pA[1];
            nb0 = pB[0]; nb1 = pB[1];
        }

        if (iter == 0) {
            #pragma unroll
            for (int half_sel = 0; half_sel < 2; half_sel++) {
                const __half2* v2 = (const __half2*)(half_sel ? &rb0 : &ra0);
                const __half2* v3 = (const __half2*)(half_sel ? &rb1 : &ra1);
                #pragma unroll
                for (int d2 = 0; d2 < 4; d2++) {
                    float2 f = __half22float2(v2[d2]);
                    acc[2 * d2]     += f.x;
                    acc[2 * d2 + 1] += f.y;
                    float2 g = __half22float2(v3[d2]);
                    acc[8 + 2 * d2]     += g.x;
                    acc[8 + 2 * d2 + 1] += g.y;
                }
            }
        } else {
            // Agreement dots for both i's (independent chains, ILP)
            __half2 hA = __hmul2(((const __half2*)&ra0)[0], vout2[0]);
            __half2 hB = __hmul2(((const __half2*)&rb0)[0], vout2[0]);
            #pragma unroll
            for (int d2 = 1; d2 < 4; d2++) {
                hA = __hfma2(((const __half2*)&ra0)[d2], vout2[d2], hA);
                hB = __hfma2(((const __half2*)&rb0)[d2], vout2[d2], hB);
            }
            #pragma unroll
            for (int d2 = 0; d2 < 4; d2++) {
                hA = __hfma2(((const __half2*)&ra1)[d2], vout2[4 + d2], hA);
                hB = __hfma2(((const __half2*)&rb1)[d2], vout2[4 + d2], hB);
            }
            float eA = __expf(__low2float(hA) + __high2float(hA));
            float eB = __expf(__low2float(hB) + __high2float(hB));

            float sA = eA, sB = eB;   // interleaved butterflies (no max pass)
            #pragma unroll
            for (int o = 16; o; o >>= 1) {
                sA += __shfl_xor_sync(0xffffffffu, sA, o);
                sB += __shfl_xor_sync(0xffffffffu, sB, o);
            }
            float cA = eA / sA;
            float cB = eB / sB;

            #pragma unroll
            for (int d2 = 0; d2 < 4; d2++) {
                float2 f = __half22float2(((const __half2*)&ra0)[d2]);
                acc[2 * d2]     = fmaf(cA, f.x, acc[2 * d2]);
                acc[2 * d2 + 1] = fmaf(cA, f.y, acc[2 * d2 + 1]);
                float2 g = __half22float2(((const __half2*)&ra1)[d2]);
                acc[8 + 2 * d2]     = fmaf(cA, g.x, acc[8 + 2 * d2]);
                acc[8 + 2 * d2 + 1] = fmaf(cA, g.y, acc[8 + 2 * d2 + 1]);
            }
            #pragma unroll
            for (int d2 = 0; d2 < 4; d2++) {
                float2 f = __half22float2(((const __half2*)&rb0)[d2]);
                acc[2 * d2]     = fmaf(cB, f.x, acc[2 * d2]);
                acc[2 * d2 + 1] = fmaf(cB, f.y, acc[2 * d2 + 1]);
                float2 g = __half22float2(((const __half2*)&rb1)[d2]);
                acc[8 + 2 * d2]     = fmaf(cB, g.x, acc[8 + 2 * d2]);
                acc[8 + 2 * d2 + 1] = fmaf(cB, g.y, acc[8 + 2 * d2 + 1]);
            }
        }

        if (step < 3) {
            ra0 = na0; ra1 = na1;
            rb0 = nb0; rb1 = nb1;
        }
    }

    if (iter == 0) {
        #pragma unroll
        for (int d = 0; d < 16; d++) acc[d] *= (1.0f / NUM_CAPS);
    }

    // Cross-warp reduce (d-major in smem: conflict-free)
    __shared__ float red[8][JD];
    #pragma unroll
    for (int d = 0; d < 16; d++) red[w][d * 32 + lane] = acc[d];
    __syncthreads();

    float s1 = 0.f, s2 = 0.f;
    #pragma unroll
    for (int ww = 0; ww < 8; ww++) {
        s1 += red[ww][t];
        s2 += red[ww][t + 256];
    }
    float* sp = g_spart + ((size_t)b * NIC + ic) * JD;
    sp[t]       = s1;
    sp[t + 256] = s2;
}

// ---------------------------------------------------------------------------
// Squash (half-batch): grid (BHALF, 4), 128 threads. Block q owns 8 j's.
// which: 0 -> g_out0, 1 -> g_out1, 2 -> dout (permuted to [b][j][d]).
// ---------------------------------------------------------------------------
__global__ __launch_bounds__(128) void squash_kernel(int which, float* __restrict__ dout, int b0)
{
    const int b    = b0 + blockIdx.x;
    const int q    = blockIdx.y;
    const int t    = threadIdx.x;       // 0..127
    const int jloc = t & 7;
    const int d    = t >> 3;            // 0..15
    const int j    = q * 8 + jloc;
    const int pos  = d * 32 + j;        // d-major position

    const float* sp = g_spart + (size_t)b * NIC * JD + pos;
    float s = 0.f;
    #pragma unroll
    for (int p = 0; p < NIC; p++) s += sp[(size_t)p * JD];

    __shared__ float s2s[8];
    if (t < 8) s2s[t] = 0.f;
    __syncthreads();
    atomicAdd(&s2s[jloc], s * s);
    __syncthreads();

    float s2 = s2s[jloc];
    float scale = s2 / ((1.0f + s2) * sqrtf(s2 + 1e-7f));
    float v = s * scale;

    if (which == 2)      dout[(size_t)b * JD + j * 16 + d] = v;
    else if (which == 0) g_out0[(size_t)b * JD + pos] = v;
    else                 g_out1[(size_t)b * JD + pos] = v;
}

// ---------------------------------------------------------------------------
extern "C" void kernel_launch(void* const* d_in, const int* in_sizes, int n_in,
                              void* d_out, int out_size)
{
    const float* x = (const float*)d_in[0];
    const float* W = (const float*)d_in[1];
    if (in_sizes[0] == (int)((size_t)IN_CAPS * NUM_CAPS * IN_DIM * OUT_DIM)) {
        const float* tmp = x; x = W; W = tmp;
    }
    float* out = (float*)d_out;

    dim3 ig(NIC, BHALF);
    dim3 sg(BHALF, 4);

    // Batch-tiled pipeline: each 32-b half's u_hat slice (64 MB) stays
    // L2-resident across its whole uhat -> iter0/1/2 chain.
    for (int h = 0; h < BATCH / BHALF; h++) {
        const int b0 = h * BHALF;

        uhat_kernel<<<IN_CAPS, 512>>>(x, W, b0);

        iter_kernel<<<ig, 256>>>(0, 1, b0);       // reverse
        squash_kernel<<<sg, 128>>>(0, out, b0);   // -> g_out0

        iter_kernel<<<ig, 256>>>(1, 0, b0);       // forward
        squash_kernel<<<sg, 128>>>(1, out, b0);   // -> g_out1

        iter_kernel<<<ig, 256>>>(2, 1, b0);       // reverse
        squash_kernel<<<sg, 128>>>(2, out, b0);   // -> dout
    }
}

// round 16
// speedup vs baseline: 1.0724x; 1.0724x over previous
#include <cuda_runtime.h>
#include <cuda_fp16.h>
#include <math.h>

// Problem constants
#define BATCH    64
#define IN_CAPS  2048
#define IN_DIM   16
#define NUM_CAPS 32
#define OUT_DIM  16
#define JD       512            // NUM_CAPS * OUT_DIM
#define NIC      32             // i-chunks per batch in iter kernel
#define IC       (IN_CAPS/NIC)  // 64 i's per block

// Scratch (device globals; allocation-free per harness rules)
__device__ __align__(16) __half g_uhat[(size_t)BATCH * IN_CAPS * JD];  // 128 MB, [b][i][j*16+d]
__device__ float g_spart[(size_t)BATCH * NIC * JD];  // 4 MB, d-major [b][ic][d*32+j]
__device__ float g_out0[(size_t)BATCH * JD];         // d-major [b][d*32+j]
__device__ float g_out1[(size_t)BATCH * JD];

// ---- packed f32x2 helpers (sm_103a) ---------------------------------------
static __device__ __forceinline__ unsigned long long pack2(float lo, float hi) {
    unsigned long long r;
    asm("mov.b64 %0, {%1, %2};" : "=l"(r) : "f"(lo), "f"(hi));
    return r;
}
#define FMA2(d, a, b, c) asm("fma.rn.f32x2 %0, %1, %2, %3;" : "=l"(d) : "l"(a), "l"(b), "l"(c))
#define MUL2(d, a, b)    asm("mul.rn.f32x2 %0, %1, %2;"     : "=l"(d) : "l"(a), "l"(b))

// ---------------------------------------------------------------------------
// K1 (proven R9/R12 config): u_hat[b,i,jd] = sum_k W[i,jd,k] * x[b,i,k].
// One block per i, 512 threads (t = jd). x staged in smem pre-packed as
// (b, b+1) f32x2 pairs; W row held in regs as (w,w) pairs. fma.rn.f32x2
// computes 2 batches per 16 packed FMAs. Coalesced W float4 reads.
// ---------------------------------------------------------------------------
__global__ __launch_bounds__(512) void uhat_kernel(
    const float* __restrict__ x, const float* __restrict__ W)
{
    const int i = blockIdx.x;
    const int t = threadIdx.x;          // 0..511

    __shared__ unsigned long long xp[32][16];   // 32 b-pairs x 16 k

    {
        int p = t >> 4, k = t & 15;     // 512 threads cover all 32*16
        float lo = x[((size_t)(2 * p)     * IN_CAPS + i) * IN_DIM + k];
        float hi = x[((size_t)(2 * p + 1) * IN_CAPS + i) * IN_DIM + k];
        xp[p][k] = pack2(lo, hi);
    }

    const float4* Wr = (const float4*)(W + ((size_t)i * JD + t) * IN_DIM);
    float4 w0 = Wr[0], w1 = Wr[1], w2 = Wr[2], w3 = Wr[3];
    unsigned long long wp[16];
    wp[0]  = pack2(w0.x, w0.x); wp[1]  = pack2(w0.y, w0.y);
    wp[2]  = pack2(w0.z, w0.z); wp[3]  = pack2(w0.w, w0.w);
    wp[4]  = pack2(w1.x, w1.x); wp[5]  = pack2(w1.y, w1.y);
    wp[6]  = pack2(w1.z, w1.z); wp[7]  = pack2(w1.w, w1.w);
    wp[8]  = pack2(w2.x, w2.x); wp[9]  = pack2(w2.y, w2.y);
    wp[10] = pack2(w2.z, w2.z); wp[11] = pack2(w2.w, w2.w);
    wp[12] = pack2(w3.x, w3.x); wp[13] = pack2(w3.y, w3.y);
    wp[14] = pack2(w3.z, w3.z); wp[15] = pack2(w3.w, w3.w);

    __syncthreads();

    __half* out = g_uhat + (size_t)i * JD + t;
    #pragma unroll 4
    for (int p = 0; p < 32; p++) {
        const ulonglong2* ap = (const ulonglong2*)xp[p];
        ulonglong2 a0 = ap[0], a1 = ap[1], a2 = ap[2], a3 = ap[3];
        ulonglong2 a4 = ap[4], a5 = ap[5], a6 = ap[6], a7 = ap[7];
        unsigned long long acc;
        MUL2(acc, wp[0],  a0.x);
        FMA2(acc, wp[1],  a0.y, acc);
        FMA2(acc, wp[2],  a1.x, acc);
        FMA2(acc, wp[3],  a1.y, acc);
        FMA2(acc, wp[4],  a2.x, acc);
        FMA2(acc, wp[5],  a2.y, acc);
        FMA2(acc, wp[6],  a3.x, acc);
        FMA2(acc, wp[7],  a3.y, acc);
        FMA2(acc, wp[8],  a4.x, acc);
        FMA2(acc, wp[9],  a4.y, acc);
        FMA2(acc, wp[10], a5.x, acc);
        FMA2(acc, wp[11], a5.y, acc);
        FMA2(acc, wp[12], a6.x, acc);
        FMA2(acc, wp[13], a6.y, acc);
        FMA2(acc, wp[14], a7.x, acc);
        FMA2(acc, wp[15], a7.y, acc);
        float lo, hi;
        asm("mov.b64 {%0, %1}, %2;" : "=f"(lo), "=f"(hi) : "l"(acc));
        out[(size_t)(2 * p)     * IN_CAPS * JD] = __float2half_rn(lo);
        out[(size_t)(2 * p + 1) * IN_CAPS * JD] = __float2half_rn(hi);
    }
}

// ---------------------------------------------------------------------------
// Fused routing iteration, COALESCED-LANE version + pipelining + ping-pong.
// Lane = 2*jA + dh: each lane loads 16B at lane*16 -> warp LDG spans 512B
// = 4 cache lines (minimum), halving L1tex wavefronts vs the j-lane layout.
// Per i: loadA covers j 0..15, loadB j 16..31 (same i). Agreement dot in
// half2 over the lane's 8 d's; pair-shuffle (xor 1) merges d-halves; the
// j-softmax sum needs only xor {2,4,8,16} (each parity class holds every j
// once). Softmax without max subtraction (exact). Two i's per step, next
// step prefetched (8 outstanding LDG.128).
// iter1 logits = <u,out0>; iter2 = <u,out0+out1>.
// ---------------------------------------------------------------------------
__global__ __launch_bounds__(256, 3) void iter_kernel(int iter, int rev)
{
    const int b     = rev ? (BATCH - 1 - blockIdx.y) : blockIdx.y;
    const int ic    = rev ? (NIC - 1 - blockIdx.x)   : blockIdx.x;
    const int t     = threadIdx.x;
    const int w     = t >> 5;
    const int lane  = t & 31;
    const int jA    = lane >> 1;        // j 0..15 for loadA
    const int jB    = jA + 16;          // j 16..31 for loadB
    const int dbase = (lane & 1) * 8;   // this lane's d range
    const int i0    = ic * IC;

    __half2 vA2[4], vB2[4];
    if (iter > 0) {
        #pragma unroll
        for (int q = 0; q < 4; q++) {
            const int d0 = dbase + 2 * q, d1 = d0 + 1;
            float a0 = g_out0[(size_t)b * JD + d0 * 32 + jA];
            float a1 = g_out0[(size_t)b * JD + d1 * 32 + jA];
            float c0 = g_out0[(size_t)b * JD + d0 * 32 + jB];
            float c1 = g_out0[(size_t)b * JD + d1 * 32 + jB];
            if (iter == 2) {
                a0 += g_out1[(size_t)b * JD + d0 * 32 + jA];
                a1 += g_out1[(size_t)b * JD + d1 * 32 + jA];
                c0 += g_out1[(size_t)b * JD + d0 * 32 + jB];
                c1 += g_out1[(size_t)b * JD + d1 * 32 + jB];
            }
            vA2[q] = __floats2half2_rn(a0, a1);
            vB2[q] = __floats2half2_rn(c0, c1);
        }
    }

    float accA[8], accB[8];
    #pragma unroll
    for (int k = 0; k < 8; k++) { accA[k] = 0.f; accB[k] = 0.f; }

    // lane-linear base: byte offset lane*16 within each i's 1KB row
    const __half* ub = g_uhat + ((size_t)b * IN_CAPS + i0) * JD + lane * 8;

    // prologue: loads for step 0 (i1 = w, i2 = w+8)
    uint4 r1A, r1B, r2A, r2B;
    r1A = *(const uint4*)(ub + (size_t)w * JD);
    r1B = *(const uint4*)(ub + (size_t)w * JD + 256);
    r2A = *(const uint4*)(ub + (size_t)(w + 8) * JD);
    r2B = *(const uint4*)(ub + (size_t)(w + 8) * JD + 256);

    #pragma unroll
    for (int step = 0; step < 4; step++) {
        uint4 n1A, n1B, n2A, n2B;
        if (step < 3) {     // prefetch step+1 before consuming current
            const int i1n = w + (step + 1) * 16;
            n1A = *(const uint4*)(ub + (size_t)i1n * JD);
            n1B = *(const uint4*)(ub + (size_t)i1n * JD + 256);
            n2A = *(const uint4*)(ub + (size_t)(i1n + 8) * JD);
            n2B = *(const uint4*)(ub + (size_t)(i1n + 8) * JD + 256);
        }

        const __half2* u1A = (const __half2*)&r1A;
        const __half2* u1B = (const __half2*)&r1B;
        const __half2* u2A = (const __half2*)&r2A;
        const __half2* u2B = (const __half2*)&r2B;

        if (iter == 0) {
            #pragma unroll
            for (int q = 0; q < 4; q++) {
                float2 f, g;
                f = __half22float2(u1A[q]); accA[2*q] += f.x; accA[2*q+1] += f.y;
                g = __half22float2(u1B[q]); accB[2*q] += g.x; accB[2*q+1] += g.y;
                f = __half22float2(u2A[q]); accA[2*q] += f.x; accA[2*q+1] += f.y;
                g = __half22float2(u2B[q]); accB[2*q] += g.x; accB[2*q+1] += g.y;
            }
        } else {
            // agreement partial dots (4 independent chains)
            __half2 h1A = __hmul2(u1A[0], vA2[0]);
            __half2 h1B = __hmul2(u1B[0], vB2[0]);
            __half2 h2A = __hmul2(u2A[0], vA2[0]);
            __half2 h2B = __hmul2(u2B[0], vB2[0]);
            #pragma unroll
            for (int q = 1; q < 4; q++) {
                h1A = __hfma2(u1A[q], vA2[q], h1A);
                h1B = __hfma2(u1B[q], vB2[q], h1B);
                h2A = __hfma2(u2A[q], vA2[q], h2A);
                h2B = __hfma2(u2B[q], vB2[q], h2B);
            }
            float p1A = __low2float(h1A) + __high2float(h1A);
            float p1B = __low2float(h1B) + __high2float(h1B);
            float p2A = __low2float(h2A) + __high2float(h2A);
            float p2B = __low2float(h2B) + __high2float(h2B);
            // merge d-halves (pair shuffle)
            p1A += __shfl_xor_sync(0xffffffffu, p1A, 1);
            p1B += __shfl_xor_sync(0xffffffffu, p1B, 1);
            p2A += __shfl_xor_sync(0xffffffffu, p2A, 1);
            p2B += __shfl_xor_sync(0xffffffffu, p2B, 1);

            float e1 = __expf(p1A), f1 = __expf(p1B);
            float e2 = __expf(p2A), f2 = __expf(p2B);

            // softmax sums: xor {2,4,8,16} sweeps all 32 j's per parity class
            float s1 = e1 + f1, s2 = e2 + f2;
            #pragma unroll
            for (int o = 16; o >= 2; o >>= 1) {
                s1 += __shfl_xor_sync(0xffffffffu, s1, o);
                s2 += __shfl_xor_sync(0xffffffffu, s2, o);
            }
            float c1A = e1 / s1, c1B = f1 / s1;
            float c2A = e2 / s2, c2B = f2 / s2;

            #pragma unroll
            for (int q = 0; q < 4; q++) {
                float2 f, g;
                f = __half22float2(u1A[q]);
                accA[2*q]   = fmaf(c1A, f.x, accA[2*q]);
                accA[2*q+1] = fmaf(c1A, f.y, accA[2*q+1]);
                g = __half22float2(u1B[q]);
                accB[2*q]   = fmaf(c1B, g.x, accB[2*q]);
                accB[2*q+1] = fmaf(c1B, g.y, accB[2*q+1]);
                f = __half22float2(u2A[q]);
                accA[2*q]   = fmaf(c2A, f.x, accA[2*q]);
                accA[2*q+1] = fmaf(c2A, f.y, accA[2*q+1]);
                g = __half22float2(u2B[q]);
                accB[2*q]   = fmaf(c2B, g.x, accB[2*q]);
                accB[2*q+1] = fmaf(c2B, g.y, accB[2*q+1]);
            }
        }

        if (step < 3) {
            r1A = n1A; r1B = n1B;
            r2A = n2A; r2B = n2B;
        }
    }

    if (iter == 0) {
        #pragma unroll
        for (int k = 0; k < 8; k++) {
            accA[k] *= (1.0f / NUM_CAPS);
            accB[k] *= (1.0f / NUM_CAPS);
        }
    }

    // Cross-warp reduce (d-major in smem). accA[k] -> (jA, dbase+k),
    // accB[k] -> (jB, dbase+k); 2-way bank conflict on writes (acceptable).
    __shared__ float red[8][JD];
    #pragma unroll
    for (int k = 0; k < 8; k++) {
        red[w][(dbase + k) * 32 + jA] = accA[k];
        red[w][(dbase + k) * 32 + jB] = accB[k];
    }
    __syncthreads();

    float s1 = 0.f, s2 = 0.f;
    #pragma unroll
    for (int ww = 0; ww < 8; ww++) {
        s1 += red[ww][t];
        s2 += red[ww][t + 256];
    }
    float* sp = g_spart + ((size_t)b * NIC + ic) * JD;
    sp[t]       = s1;
    sp[t + 256] = s2;
}

// ---------------------------------------------------------------------------
// Reduce partials over NIC chunks + squash (proven R12 version).
// d-major positions: t = d*32 + j.
// which: 0 -> g_out0, 1 -> g_out1, 2 -> dout (permuted to [b][j][d]).
// ---------------------------------------------------------------------------
__global__ __launch_bounds__(512) void squash_kernel(int which, float* __restrict__ dout)
{
    const int b = blockIdx.x;
    const int t = threadIdx.x;

    const float* sp = g_spart + (size_t)b * NIC * JD + t;
    float s = 0.f;
    #pragma unroll
    for (int p = 0; p < NIC; p++) s += sp[(size_t)p * JD];

    __shared__ float s2s[NUM_CAPS];
    if (t < NUM_CAPS) s2s[t] = 0.f;
    __syncthreads();
    atomicAdd(&s2s[t & 31], s * s);
    __syncthreads();

    float s2 = s2s[t & 31];
    float scale = s2 / ((1.0f + s2) * sqrtf(s2 + 1e-7f));
    float v = s * scale;

    if (which == 2)      dout[(size_t)b * JD + (t & 31) * 16 + (t >> 5)] = v;
    else if (which == 0) g_out0[(size_t)b * JD + t] = v;
    else                 g_out1[(size_t)b * JD + t] = v;
}

// ---------------------------------------------------------------------------
extern "C" void kernel_launch(void* const* d_in, const int* in_sizes, int n_in,
                              void* d_out, int out_size)
{
    const float* x = (const float*)d_in[0];
    const float* W = (const float*)d_in[1];
    if (in_sizes[0] == (int)((size_t)IN_CAPS * NUM_CAPS * IN_DIM * OUT_DIM)) {
        const float* tmp = x; x = W; W = tmp;
    }
    float* out = (float*)d_out;

    dim3 ig(NIC, BATCH);

    // L2 ping-pong: uhat ascending-i; alternate direction each pass so every
    // pass starts on the L2-resident tail of the previous one.
    uhat_kernel<<<IN_CAPS, 512>>>(x, W);

    iter_kernel<<<ig, 256>>>(0, 1);          // reverse
    squash_kernel<<<BATCH, 512>>>(0, out);   // -> g_out0

    iter_kernel<<<ig, 256>>>(1, 0);          // forward
    squash_kernel<<<BATCH, 512>>>(1, out);   // -> g_out1

    iter_kernel<<<ig, 256>>>(2, 1);          // reverse
    squash_kernel<<<BATCH, 512>>>(2, out);   // -> dout
}